// round 14
// baseline (speedup 1.0000x reference)
#include <cuda_runtime.h>
#include <cuda_fp16.h>
#include <math.h>

#define NNODES 50000
#define NEDGES 1200000
#define SCAN_TILE 1024
#define SCAN_BLOCKS ((NNODES + SCAN_TILE - 1) / SCAN_TILE)

// ---------------- scratch (device globals: no allocation allowed) ----------------
__device__ float g_in8[NNODES * 8];
__device__ float g_t1[NNODES * 128];
__device__ float g_t2[NNODES * 128];
__device__ float g_h[NNODES * 64];      // current node features
__device__ float g_D[NNODES * 128];     // packed dst proj fp32; f-halves pre-scaled by 0.5
__device__ unsigned g_Sh[NNODES * 64];  // packed src proj fp16: [2l]=h2(f)*0.5, [2l+1]=h2(s)
__device__ float g_t3[NNODES * 64];     // readout hidden
__device__ int   g_cnt[NNODES * 2];     // [deg | cursor]
__device__ int   g_rowstart[NNODES + 1];
__device__ int   g_blocksum[SCAN_BLOCKS + 1];
__device__ uint4 g_E[NEDGES];           // {src | klo<<20, h2(g0,g1), h2(g2,g3), h2(g4,0)}

__device__ __forceinline__ unsigned h2_bits(__half2 h) { return *reinterpret_cast<unsigned*>(&h); }
__device__ __forceinline__ __half2 bits_h2(unsigned u) { return *reinterpret_cast<__half2*>(&u); }

__device__ __forceinline__ void ldsm4(unsigned& r0, unsigned& r1, unsigned& r2, unsigned& r3, unsigned addr) {
    asm volatile("ldmatrix.sync.aligned.m8n8.x4.shared.b16 {%0,%1,%2,%3}, [%4];"
                 : "=r"(r0), "=r"(r1), "=r"(r2), "=r"(r3) : "r"(addr));
}
__device__ __forceinline__ void ldsm4t(unsigned& r0, unsigned& r1, unsigned& r2, unsigned& r3, unsigned addr) {
    asm volatile("ldmatrix.sync.aligned.m8n8.x4.trans.shared.b16 {%0,%1,%2,%3}, [%4];"
                 : "=r"(r0), "=r"(r1), "=r"(r2), "=r"(r3) : "r"(addr));
}
__device__ __forceinline__ void mma16816(float* c, unsigned a0, unsigned a1, unsigned a2, unsigned a3,
                                         unsigned b0, unsigned b1) {
    asm volatile("mma.sync.aligned.m16n8k16.row.col.f32.f16.f16.f32 "
                 "{%0,%1,%2,%3}, {%4,%5,%6,%7}, {%8,%9}, {%0,%1,%2,%3};"
                 : "+f"(c[0]), "+f"(c[1]), "+f"(c[2]), "+f"(c[3])
                 : "r"(a0), "r"(a1), "r"(a2), "r"(a3), "r"(b0), "r"(b1));
}

// dynamic smem layout for convproj (hi/lo split tiles)
#define CP_A_BYTES (64 * 72 * 2)      // 9216
#define CP_B_BYTES (64 * 264 * 2)     // 33792
#define CP_DYN_TOTAL (2 * (CP_A_BYTES + CP_B_BYTES))  // 86016

// ---------------- concat [x|forces_stack|forces_norm] -> [N,8] ----------------
__global__ void concat_kernel(const float* __restrict__ x, const float* __restrict__ fs,
                              const float* __restrict__ fn, float* __restrict__ out, int n) {
    int i = blockIdx.x * blockDim.x + threadIdx.x;
    if (i >= n) return;
    float4 xv = *reinterpret_cast<const float4*>(&x[i * 4]);
    out[i * 8 + 0] = xv.x;
    out[i * 8 + 1] = xv.y;
    out[i * 8 + 2] = xv.z;
    out[i * 8 + 3] = xv.w;
    out[i * 8 + 4] = fs[i * 3 + 0];
    out[i * 8 + 5] = fs[i * 3 + 1];
    out[i * 8 + 6] = fs[i * 3 + 2];
    out[i * 8 + 7] = fn[i];
}

// ---------------- CSR build ----------------
__global__ void zero_int_kernel(int* __restrict__ p, int n) {
    int i = blockIdx.x * blockDim.x + threadIdx.x;
    if (i < n) p[i] = 0;
}

__global__ void hist_kernel(const int* __restrict__ dst, int* __restrict__ deg, int ne) {
    int e = blockIdx.x * blockDim.x + threadIdx.x;
    if (e < ne) atomicAdd(&deg[dst[e]], 1);
}

__global__ void scanA_kernel(const int* __restrict__ deg, int* __restrict__ rowstart,
                             int* __restrict__ blocksum, int nN) {
    __shared__ int warpsums[32];
    int tid = threadIdx.x;
    int lane = tid & 31, wid = tid >> 5;
    int i = blockIdx.x * SCAN_TILE + tid;
    int v = (i < nN) ? deg[i] : 0;
    int x = v;
#pragma unroll
    for (int o = 1; o < 32; o <<= 1) {
        int t = __shfl_up_sync(0xffffffffu, x, o);
        if (lane >= o) x += t;
    }
    if (lane == 31) warpsums[wid] = x;
    __syncthreads();
    if (wid == 0) {
        int y = warpsums[lane];
#pragma unroll
        for (int o = 1; o < 32; o <<= 1) {
            int t = __shfl_up_sync(0xffffffffu, y, o);
            if (lane >= o) y += t;
        }
        warpsums[lane] = y;
    }
    __syncthreads();
    int incl = x + (wid ? warpsums[wid - 1] : 0);
    if (i < nN) rowstart[i] = incl;
    if (tid == SCAN_TILE - 1) blocksum[blockIdx.x] = incl;
}

// phase B: parallel exclusive scan of tile sums (nblocks <= 64)
__global__ void scanB_kernel(int* __restrict__ blocksum, int* __restrict__ rowstart,
                             int nblocks, int nN) {
    __shared__ int w0sum;
    int tid = threadIdx.x;      // 64 threads
    int lane = tid & 31;
    int v = (tid < nblocks) ? blocksum[tid] : 0;
    int x = v;
#pragma unroll
    for (int o = 1; o < 32; o <<= 1) {
        int t = __shfl_up_sync(0xffffffffu, x, o);
        if (lane >= o) x += t;
    }
    if (tid == 31) w0sum = x;
    __syncthreads();
    if (tid >= 32) x += w0sum;
    if (tid < nblocks) blocksum[tid] = x - v;   // exclusive
    if (tid == nblocks - 1) rowstart[nN] = x;   // total
}

__global__ void scanC_kernel(const int* __restrict__ deg, int* __restrict__ rowstart,
                             const int* __restrict__ blocksum, int nN) {
    int i = blockIdx.x * SCAN_TILE + threadIdx.x;
    if (i < nN) rowstart[i] = rowstart[i] - deg[i] + blocksum[blockIdx.x];
}

// scatter edges into CSR order (by dst) + precompute 5-term gaussian window (fp16 packed)
__global__ void scatter_kernel(const int* __restrict__ src, const int* __restrict__ dst,
                               const float* __restrict__ elen,
                               const int* __restrict__ rowstart, int* __restrict__ cursor,
                               uint4* __restrict__ E, int ne) {
    int e = blockIdx.x * blockDim.x + threadIdx.x;
    if (e >= ne) return;
    int dv = dst[e];
    int slot = rowstart[dv] + atomicAdd(&cursor[dv], 1);
    float d = elen[e];
    int k0 = (int)rintf(d * 5.0f);
    int klo = min(max(k0 - 2, 0), 21);
    float g[5];
#pragma unroll
    for (int j = 0; j < 5; ++j) {
        float dm = d - (float)(klo + j) * 0.2f;
        g[j] = __expf(-25.0f * dm * dm);
    }
    uint4 rec;
    rec.x = (unsigned)src[e] | ((unsigned)klo << 20);
    rec.y = h2_bits(__floats2half2_rn(g[0], g[1]));
    rec.z = h2_bits(__floats2half2_rn(g[2], g[3]));
    rec.w = h2_bits(__floats2half2_rn(g[4], 0.0f));
    E[slot] = rec;
}

// ---------------- node GEMM v2 (scalar, kept for embed layer1 only) ----------------
template <int K, int J, int YB, int NB, int KT, int ACT>
__global__ void __launch_bounds__(J * YB) gemm2_kernel(const float* __restrict__ in,
                                                       const float* __restrict__ W,
                                                       const float* __restrict__ bias,
                                                       float* __restrict__ out, int nN,
                                                       int ostride, int ocol) {
    constexpr int NBY = NB / YB;
    __shared__ float sIn[NB][K];
    __shared__ float sW[KT][J];
    int tid = threadIdx.x;
    int col = tid % J;
    int ys = tid / J;
    int nb = blockIdx.x * NB;

    for (int idx = tid * 4; idx < NB * K; idx += J * YB * 4) {
        int n = idx / K, k = idx % K;
        int gn = nb + n;
        float4 v = (gn < nN) ? *reinterpret_cast<const float4*>(&in[gn * K + k])
                             : make_float4(0.f, 0.f, 0.f, 0.f);
        *reinterpret_cast<float4*>(&sIn[n][k]) = v;
    }
    float bv = bias ? __ldg(&bias[col]) : 0.0f;
    float acc[NBY];
#pragma unroll
    for (int n = 0; n < NBY; n++) acc[n] = bv;

    for (int k0 = 0; k0 < K; k0 += KT) {
        __syncthreads();
        for (int r = ys; r < KT; r += YB) sW[r][col] = W[(k0 + r) * J + col];
        __syncthreads();
#pragma unroll
        for (int k = 0; k < KT; k += 4) {
            float w0 = sW[k][col], w1 = sW[k + 1][col], w2 = sW[k + 2][col], w3 = sW[k + 3][col];
#pragma unroll
            for (int n = 0; n < NBY; ++n) {
                float4 v = *reinterpret_cast<const float4*>(&sIn[ys * NBY + n][k0 + k]);
                float a = acc[n];
                a = fmaf(v.x, w0, a);
                a = fmaf(v.y, w1, a);
                a = fmaf(v.z, w2, a);
                a = fmaf(v.w, w3, a);
                acc[n] = a;
            }
        }
    }
#pragma unroll
    for (int n = 0; n < NBY; n++) {
        int gn = nb + ys * NBY + n;
        if (gn < nN) {
            float v = acc[n];
            if (ACT == 1) v = v > 0.0f ? v : 0.01f * v;   // leaky
            else if (ACT == 2) v = fmaxf(v, 0.0f);        // relu
            out[gn * ostride + ocol + col] = v;
        }
    }
}

// ---------------- generic split-precision MMA node GEMM ----------------
template <int K, int J, int ACT>
__global__ void __launch_bounds__(256) gemm_mma_kernel(const float* __restrict__ in,
                                                       const float* __restrict__ W,
                                                       const float* __restrict__ bias,
                                                       float* __restrict__ out, int nN) {
    constexpr int AB = 128 * 72 * 2;
    constexpr int BB = 64 * (J + 8) * 2;
    constexpr int NT8 = J / 8;
    extern __shared__ __align__(16) char dynsmem[];
    __half (*sAh)[72] = reinterpret_cast<__half(*)[72]>(dynsmem);
    __half (*sAl)[72] = reinterpret_cast<__half(*)[72]>(dynsmem + AB);
    __half (*sBh)[J + 8] = reinterpret_cast<__half(*)[J + 8]>(dynsmem + 2 * AB);
    __half (*sBl)[J + 8] = reinterpret_cast<__half(*)[J + 8]>(dynsmem + 2 * AB + BB);

    int tid = threadIdx.x;
    int nb = blockIdx.x * 128;
    int w = tid >> 5, lane = tid & 31;
    int mrow = w << 4;
    int q = lane >> 3, rr = lane & 7;

    float acc[NT8][4];
#pragma unroll
    for (int i = 0; i < NT8; ++i)
#pragma unroll
        for (int j = 0; j < 4; ++j) acc[i][j] = 0.0f;

    for (int kc = 0; kc < K; kc += 64) {
        __syncthreads();
        for (int idx = tid * 4; idx < 128 * 64; idx += 1024) {
            int n = idx >> 6, k = idx & 63;
            int gn = nb + n;
            float4 v = (gn < nN) ? *reinterpret_cast<const float4*>(&in[gn * K + kc + k])
                                 : make_float4(0.f, 0.f, 0.f, 0.f);
            __half h0 = __float2half_rn(v.x), h1 = __float2half_rn(v.y);
            __half h2v = __float2half_rn(v.z), h3 = __float2half_rn(v.w);
            *reinterpret_cast<uint2*>(&sAh[n][k]) =
                make_uint2(h2_bits(__halves2half2(h0, h1)), h2_bits(__halves2half2(h2v, h3)));
            *reinterpret_cast<uint2*>(&sAl[n][k]) = make_uint2(
                h2_bits(__halves2half2(__float2half_rn(v.x - __half2float(h0)),
                                       __float2half_rn(v.y - __half2float(h1)))),
                h2_bits(__halves2half2(__float2half_rn(v.z - __half2float(h2v)),
                                       __float2half_rn(v.w - __half2float(h3)))));
        }
        for (int idx = tid * 4; idx < 64 * J; idx += 1024) {
            int r = idx / J, j = idx % J;
            float4 v = *reinterpret_cast<const float4*>(&W[(kc + r) * J + j]);
            __half h0 = __float2half_rn(v.x), h1 = __float2half_rn(v.y);
            __half h2v = __float2half_rn(v.z), h3 = __float2half_rn(v.w);
            *reinterpret_cast<uint2*>(&sBh[r][j]) =
                make_uint2(h2_bits(__halves2half2(h0, h1)), h2_bits(__halves2half2(h2v, h3)));
            *reinterpret_cast<uint2*>(&sBl[r][j]) = make_uint2(
                h2_bits(__halves2half2(__float2half_rn(v.x - __half2float(h0)),
                                       __float2half_rn(v.y - __half2float(h1)))),
                h2_bits(__halves2half2(__float2half_rn(v.z - __half2float(h2v)),
                                       __float2half_rn(v.w - __half2float(h3)))));
        }
        __syncthreads();

#pragma unroll
        for (int ks = 0; ks < 4; ++ks) {
            int kk = ks << 4;
            unsigned a0, a1, a2, a3, c0, c1, c2, c3;
            int ar = mrow + (lane & 15), ac = kk + ((lane >> 4) << 3);
            ldsm4(a0, a1, a2, a3, (unsigned)__cvta_generic_to_shared(&sAh[ar][ac]));
            ldsm4(c0, c1, c2, c3, (unsigned)__cvta_generic_to_shared(&sAl[ar][ac]));
#pragma unroll
            for (int nt2 = 0; nt2 < J / 16; ++nt2) {
                int n0 = nt2 << 4;
                int br = kk + rr + ((q & 1) << 3), bc = n0 + ((q >> 1) << 3);
                unsigned b0, b1, b2, b3, d0, d1, d2, d3;
                ldsm4t(b0, b1, b2, b3, (unsigned)__cvta_generic_to_shared(&sBh[br][bc]));
                ldsm4t(d0, d1, d2, d3, (unsigned)__cvta_generic_to_shared(&sBl[br][bc]));
                mma16816(acc[nt2 * 2], a0, a1, a2, a3, b0, b1);
                mma16816(acc[nt2 * 2], a0, a1, a2, a3, d0, d1);
                mma16816(acc[nt2 * 2], c0, c1, c2, c3, b0, b1);
                mma16816(acc[nt2 * 2 + 1], a0, a1, a2, a3, b2, b3);
                mma16816(acc[nt2 * 2 + 1], a0, a1, a2, a3, d2, d3);
                mma16816(acc[nt2 * 2 + 1], c0, c1, c2, c3, b2, b3);
            }
        }
    }

    int r0 = lane >> 2;
    int cpair = (lane & 3) << 1;
    int gr0 = nb + mrow + r0;
    int gr1 = gr0 + 8;
#pragma unroll
    for (int nt = 0; nt < NT8; ++nt) {
        int col = (nt << 3) + cpair;
        float b0v = __ldg(&bias[col]), b1v = __ldg(&bias[col + 1]);
        float v00 = acc[nt][0] + b0v, v01 = acc[nt][1] + b1v;
        float v10 = acc[nt][2] + b0v, v11 = acc[nt][3] + b1v;
        if (ACT == 1) {
            v00 = v00 > 0.f ? v00 : 0.01f * v00;
            v01 = v01 > 0.f ? v01 : 0.01f * v01;
            v10 = v10 > 0.f ? v10 : 0.01f * v10;
            v11 = v11 > 0.f ? v11 : 0.01f * v11;
        } else if (ACT == 2) {
            v00 = fmaxf(v00, 0.f); v01 = fmaxf(v01, 0.f);
            v10 = fmaxf(v10, 0.f); v11 = fmaxf(v11, 0.f);
        }
        if (gr0 < nN) *reinterpret_cast<float2*>(&out[gr0 * J + col]) = make_float2(v00, v01);
        if (gr1 < nN) *reinterpret_cast<float2*>(&out[gr1 * J + col]) = make_float2(v10, v11);
    }
}

// ---------------- conv projections via split-precision tensor-core MMA ----------------
__global__ void __launch_bounds__(256) convproj_mma_kernel(const float* __restrict__ h,
                                                           const float* __restrict__ wf,
                                                           const float* __restrict__ bf,
                                                           const float* __restrict__ bs,
                                                           const float* __restrict__ ws,
                                                           float* __restrict__ D,
                                                           unsigned* __restrict__ Sh, int nN) {
    extern __shared__ __align__(16) char dynsmem[];
    __half (*sA)[72]  = reinterpret_cast<__half(*)[72]>(dynsmem);
    __half (*sAl)[72] = reinterpret_cast<__half(*)[72]>(dynsmem + CP_A_BYTES);
    __half (*sB)[264]  = reinterpret_cast<__half(*)[264]>(dynsmem + 2 * CP_A_BYTES);
    __half (*sBl)[264] = reinterpret_cast<__half(*)[264]>(dynsmem + 2 * CP_A_BYTES + CP_B_BYTES);
    int tid = threadIdx.x;
    int nb = blockIdx.x * 64;

    for (int idx = tid * 4; idx < 64 * 64; idx += 1024) {
        int n = idx >> 6, k = idx & 63;
        int gn = nb + n;
        float4 v = (gn < nN) ? *reinterpret_cast<const float4*>(&h[gn * 64 + k])
                             : make_float4(0.f, 0.f, 0.f, 0.f);
        __half h0 = __float2half_rn(v.x), h1 = __float2half_rn(v.y);
        __half h2v = __float2half_rn(v.z), h3 = __float2half_rn(v.w);
        __half l0 = __float2half_rn(v.x - __half2float(h0));
        __half l1 = __float2half_rn(v.y - __half2float(h1));
        __half l2 = __float2half_rn(v.z - __half2float(h2v));
        __half l3 = __float2half_rn(v.w - __half2float(h3));
        *reinterpret_cast<uint2*>(&sA[n][k]) =
            make_uint2(h2_bits(__halves2half2(h0, h1)), h2_bits(__halves2half2(h2v, h3)));
        *reinterpret_cast<uint2*>(&sAl[n][k]) =
            make_uint2(h2_bits(__halves2half2(l0, l1)), h2_bits(__halves2half2(l2, l3)));
    }
    for (int i = tid; i < 128 * 64; i += 256) {
        int r = i >> 6, j = i & 63;
        int k = r & 63;
        int half128 = (r >> 6) << 7;
        float vf = 0.5f * wf[i];
        float vs = ws[i];
        __half hf = __float2half_rn(vf);
        __half hs = __float2half_rn(vs);
        sB[k][half128 + j] = hf;
        sB[k][half128 + 64 + j] = hs;
        sBl[k][half128 + j] = __float2half_rn(vf - __half2float(hf));
        sBl[k][half128 + 64 + j] = __float2half_rn(vs - __half2float(hs));
    }
    __syncthreads();

    int w = tid >> 5, lane = tid & 31;
    int mrow = (w & 3) << 4;
    int nbase = (w >> 2) << 7;

    float acc[16][4];
#pragma unroll
    for (int i = 0; i < 16; ++i)
#pragma unroll
        for (int j = 0; j < 4; ++j) acc[i][j] = 0.0f;

    int q = lane >> 3, rr = lane & 7;
#pragma unroll
    for (int ks = 0; ks < 4; ++ks) {
        int kk = ks << 4;
        unsigned a0, a1, a2, a3, c0, c1, c2, c3;
        int ar = mrow + (lane & 15), ac = kk + ((lane >> 4) << 3);
        ldsm4(a0, a1, a2, a3, (unsigned)__cvta_generic_to_shared(&sA[ar][ac]));
        ldsm4(c0, c1, c2, c3, (unsigned)__cvta_generic_to_shared(&sAl[ar][ac]));
#pragma unroll
        for (int nt2 = 0; nt2 < 8; ++nt2) {
            int n0 = nbase + (nt2 << 4);
            int br = kk + rr + ((q & 1) << 3), bc = n0 + ((q >> 1) << 3);
            unsigned b0, b1, b2, b3, d0, d1, d2, d3;
            ldsm4t(b0, b1, b2, b3, (unsigned)__cvta_generic_to_shared(&sB[br][bc]));
            ldsm4t(d0, d1, d2, d3, (unsigned)__cvta_generic_to_shared(&sBl[br][bc]));
            mma16816(acc[nt2 * 2], a0, a1, a2, a3, b0, b1);
            mma16816(acc[nt2 * 2], a0, a1, a2, a3, d0, d1);
            mma16816(acc[nt2 * 2], c0, c1, c2, c3, b0, b1);
            mma16816(acc[nt2 * 2 + 1], a0, a1, a2, a3, b2, b3);
            mma16816(acc[nt2 * 2 + 1], a0, a1, a2, a3, d2, d3);
            mma16816(acc[nt2 * 2 + 1], c0, c1, c2, c3, b2, b3);
        }
    }

    int r0 = lane >> 2;
    int cpair = (lane & 3) << 1;
    int gr0 = nb + mrow + r0;
    int gr1 = gr0 + 8;
#pragma unroll
    for (int nt = 0; nt < 16; ++nt) {
        int nl = (nt << 3) + cpair;
        if (nbase == 0) {
            float b0v, b1v;
            int po;
            if (nl < 64) { b0v = 0.5f * __ldg(&bf[nl]); b1v = 0.5f * __ldg(&bf[nl + 1]); po = 2 * nl; }
            else         { b0v = __ldg(&bs[nl - 64]);   b1v = __ldg(&bs[nl - 63]);       po = 2 * nl - 126; }
            if (gr0 < nN)
                *reinterpret_cast<float2*>(&D[gr0 * 128 + po]) = make_float2(acc[nt][0] + b0v, acc[nt][1] + b1v);
            if (gr1 < nN)
                *reinterpret_cast<float2*>(&D[gr1 * 128 + po]) = make_float2(acc[nt][2] + b0v, acc[nt][3] + b1v);
        } else {
            int word = (nl < 64) ? nl : (nl - 63);
            if (gr0 < nN) Sh[gr0 * 64 + word] = h2_bits(__floats2half2_rn(acc[nt][0], acc[nt][1]));
            if (gr1 < nN) Sh[gr1 * 64 + word] = h2_bits(__floats2half2_rn(acc[nt][2], acc[nt][3]));
        }
    }
}

// ---------------- edge kernel: warp per dst node, software-pipelined gathers ----------------
__global__ void __launch_bounds__(256) edge2_kernel(const float4* __restrict__ D4,
                                                    const uint2* __restrict__ S2,
                                                    float* __restrict__ h,
                                                    const int* __restrict__ rowstart,
                                                    const uint4* __restrict__ E,
                                                    const float* __restrict__ wfe,
                                                    const float* __restrict__ wse,
                                                    int nN, int act) {
    __shared__ uint2 sW2[26][32];
    int tid = threadIdx.x;
    for (int idx = tid; idx < 26 * 32; idx += 256) {
        int k = idx >> 5, l = idx & 31;
        uint2 p;
        p.x = h2_bits(__floats2half2_rn(0.5f * wfe[k * 64 + 2 * l], 0.5f * wfe[k * 64 + 2 * l + 1]));
        p.y = h2_bits(__floats2half2_rn(wse[k * 64 + 2 * l], wse[k * 64 + 2 * l + 1]));
        sW2[k][l] = p;
    }
    __syncthreads();

    int lane = tid & 31;
    int node = blockIdx.x * 8 + (tid >> 5);
    if (node >= nN) return;
    int c2 = lane << 1;

    const float4 a4 = __ldg(&D4[node * 32 + lane]);  // (0.5*af.x, 0.5*af.y, as.x, as.y)
    const float2 hm = *reinterpret_cast<const float2*>(&h[node * 64 + c2]);
    float mx = 0.0f, my = 0.0f;

    int rs = __ldg(&rowstart[node]);
    int re = __ldg(&rowstart[node + 1]);

    // software pipeline: E records prefetched depth-2 (sequential addresses),
    // S gather depth-1 -> steady-state dependent-chain ~ one L2 latency, not two.
    uint4 r0v, r1v;
    uint2 b0v;
    if (rs < re) {
        r0v = __ldg(&E[rs]);
        b0v = __ldg(&S2[(r0v.x & 0xFFFFFu) * 32 + lane]);
    }
    if (rs + 1 < re) r1v = __ldg(&E[rs + 1]);

    for (int s = rs; s < re; ++s) {
        uint4 r2v;
        uint2 b1v;
        if (s + 2 < re) r2v = __ldg(&E[s + 2]);
        if (s + 1 < re) b1v = __ldg(&S2[(r1v.x & 0xFFFFFu) * 32 + lane]);

        int klo = (int)(r0v.x >> 20);
        __half2 g01 = bits_h2(r0v.y);
        __half2 g23 = bits_h2(r0v.z);
        __half2 g4h = bits_h2(r0v.w);

        __half2 ef = bits_h2(b0v.x);
        __half2 es = bits_h2(b0v.y);
        const uint2* wp = &sW2[klo][lane];
        uint2 wv;
        __half2 gb;
        wv = wp[0];   gb = __low2half2(g01);  ef = __hfma2(gb, bits_h2(wv.x), ef); es = __hfma2(gb, bits_h2(wv.y), es);
        wv = wp[32];  gb = __high2half2(g01); ef = __hfma2(gb, bits_h2(wv.x), ef); es = __hfma2(gb, bits_h2(wv.y), es);
        wv = wp[64];  gb = __low2half2(g23);  ef = __hfma2(gb, bits_h2(wv.x), ef); es = __hfma2(gb, bits_h2(wv.y), es);
        wv = wp[96];  gb = __high2half2(g23); ef = __hfma2(gb, bits_h2(wv.x), ef); es = __hfma2(gb, bits_h2(wv.y), es);
        wv = wp[128]; gb = __low2half2(g4h);  ef = __hfma2(gb, bits_h2(wv.x), ef); es = __hfma2(gb, bits_h2(wv.y), es);

        float2 ef2 = __half22float2(ef);
        float2 es2 = __half22float2(es);
        float zfx = a4.x + ef2.x;   // already z/2 for the sigmoid channel
        float zfy = a4.y + ef2.y;
        float zsx = a4.z + es2.x;
        float zsy = a4.w + es2.y;

        float tx, ty;
        asm("tanh.approx.f32 %0, %1;" : "=f"(tx) : "f"(zfx));
        asm("tanh.approx.f32 %0, %1;" : "=f"(ty) : "f"(zfy));
        float sgx = fmaf(tx, 0.5f, 0.5f);
        float sgy = fmaf(ty, 0.5f, 0.5f);
        float spx = (zsx > 15.0f) ? zsx : __logf(1.0f + __expf(zsx));
        float spy = (zsy > 15.0f) ? zsy : __logf(1.0f + __expf(zsy));

        mx = fmaf(sgx, spx, mx);
        my = fmaf(sgy, spy, my);

        r0v = r1v; r1v = r2v; b0v = b1v;
    }
    float ox = hm.x + mx, oy = hm.y + my;
    if (act) {
        ox = ox > 0.0f ? ox : 0.01f * ox;
        oy = oy > 0.0f ? oy : 0.01f * oy;
    }
    *reinterpret_cast<float2*>(&h[node * 64 + c2]) = make_float2(ox, oy);
}

// ---------------- readout layer 2: [N,64] @ [64,3] + b, warp per node ----------------
__global__ void desc2_kernel(const float* __restrict__ t3, const float* __restrict__ w2,
                             const float* __restrict__ b2, float* __restrict__ out, int n) {
    __shared__ float sw[192];
    __shared__ float sb[3];
    if (threadIdx.x < 192) sw[threadIdx.x] = w2[threadIdx.x];
    if (threadIdx.x < 3) sb[threadIdx.x] = b2[threadIdx.x];
    __syncthreads();
    int lane = threadIdx.x & 31;
    int gw = blockIdx.x * (blockDim.x >> 5) + (threadIdx.x >> 5);
    int nw = gridDim.x * (blockDim.x >> 5);
    for (int node = gw; node < n; node += nw) {
        float p0 = 0.f, p1 = 0.f, p2 = 0.f;
        for (int k = lane; k < 64; k += 32) {
            float v = t3[node * 64 + k];
            p0 = fmaf(v, sw[k * 3 + 0], p0);
            p1 = fmaf(v, sw[k * 3 + 1], p1);
            p2 = fmaf(v, sw[k * 3 + 2], p2);
        }
        for (int off = 16; off; off >>= 1) {
            p0 += __shfl_down_sync(0xffffffffu, p0, off);
            p1 += __shfl_down_sync(0xffffffffu, p1, off);
            p2 += __shfl_down_sync(0xffffffffu, p2, off);
        }
        if (lane == 0) {
            out[node * 3 + 0] = p0 + sb[0];
            out[node * 3 + 1] = p1 + sb[1];
            out[node * 3 + 2] = p2 + sb[2];
        }
    }
}

extern "C" void kernel_launch(void* const* d_in, const int* in_sizes, int n_in,
                              void* d_out, int out_size) {
    const float* x    = (const float*)d_in[0];
    const float* fs   = (const float*)d_in[1];
    const float* fn   = (const float*)d_in[2];
    const int*   eidx = (const int*)d_in[3];
    const float* elen = (const float*)d_in[4];
    const float* ew1 = (const float*)d_in[5];  const float* eb1 = (const float*)d_in[6];
    const float* ew2 = (const float*)d_in[7];  const float* eb2 = (const float*)d_in[8];
    const float* ew3 = (const float*)d_in[9];  const float* eb3 = (const float*)d_in[10];
    const float* dw1 = (const float*)d_in[23]; const float* db1 = (const float*)d_in[24];
    const float* dw2 = (const float*)d_in[25]; const float* db2 = (const float*)d_in[26];

    int nN = in_sizes[0] / 4;
    int nE = in_sizes[4];
    const int* src = eidx;
    const int* dst = eidx + nE;

    float *p_in8, *p_t1, *p_t2, *p_h, *p_D, *p_t3;
    unsigned* p_Sh;
    int *p_cnt, *p_rowstart, *p_blocksum;
    uint4* p_E;
    cudaGetSymbolAddress((void**)&p_in8, g_in8);
    cudaGetSymbolAddress((void**)&p_t1, g_t1);
    cudaGetSymbolAddress((void**)&p_t2, g_t2);
    cudaGetSymbolAddress((void**)&p_h, g_h);
    cudaGetSymbolAddress((void**)&p_D, g_D);
    cudaGetSymbolAddress((void**)&p_Sh, g_Sh);
    cudaGetSymbolAddress((void**)&p_t3, g_t3);
    cudaGetSymbolAddress((void**)&p_cnt, g_cnt);
    cudaGetSymbolAddress((void**)&p_rowstart, g_rowstart);
    cudaGetSymbolAddress((void**)&p_blocksum, g_blocksum);
    cudaGetSymbolAddress((void**)&p_E, g_E);

    // dynamic smem opt-ins (host-side, capture-safe)
    cudaFuncSetAttribute(convproj_mma_kernel, cudaFuncAttributeMaxDynamicSharedMemorySize,
                         CP_DYN_TOTAL);
    constexpr int G128_SMEM = 2 * (128 * 72 * 2) + 2 * (64 * 136 * 2);  // 71680
    constexpr int G64_SMEM  = 2 * (128 * 72 * 2) + 2 * (64 * 72 * 2);   // 55296
    cudaFuncSetAttribute((const void*)gemm_mma_kernel<128, 128, 1>,
                         cudaFuncAttributeMaxDynamicSharedMemorySize, G128_SMEM);
    cudaFuncSetAttribute((const void*)gemm_mma_kernel<128, 64, 1>,
                         cudaFuncAttributeMaxDynamicSharedMemorySize, G64_SMEM);
    cudaFuncSetAttribute((const void*)gemm_mma_kernel<64, 64, 2>,
                         cudaFuncAttributeMaxDynamicSharedMemorySize, G64_SMEM);

    int* p_deg = p_cnt;
    int* p_cur = p_cnt + NNODES;
    int nsb = (nN + SCAN_TILE - 1) / SCAN_TILE;

    // ---- fork: CSR chain on side stream, embed chain on main stream ----
    cudaStream_t sCsr;
    cudaEvent_t evFork, evJoin;
    cudaStreamCreateWithFlags(&sCsr, cudaStreamNonBlocking);
    cudaEventCreateWithFlags(&evFork, cudaEventDisableTiming);
    cudaEventCreateWithFlags(&evJoin, cudaEventDisableTiming);
    cudaEventRecord(evFork, 0);
    cudaStreamWaitEvent(sCsr, evFork, 0);

    // CSR chain (side stream)
    zero_int_kernel<<<(2 * nN + 255) / 256, 256, 0, sCsr>>>(p_cnt, 2 * nN);
    hist_kernel<<<(nE + 255) / 256, 256, 0, sCsr>>>(dst, p_deg, nE);
    scanA_kernel<<<nsb, SCAN_TILE, 0, sCsr>>>(p_deg, p_rowstart, p_blocksum, nN);
    scanB_kernel<<<1, 64, 0, sCsr>>>(p_blocksum, p_rowstart, nsb, nN);
    scanC_kernel<<<nsb, SCAN_TILE, 0, sCsr>>>(p_deg, p_rowstart, p_blocksum, nN);
    scatter_kernel<<<(nE + 255) / 256, 256, 0, sCsr>>>(src, dst, elen, p_rowstart, p_cur, p_E, nE);
    cudaEventRecord(evJoin, sCsr);

    // embed chain (main stream)
    concat_kernel<<<(nN + 255) / 256, 256>>>(x, fs, fn, p_in8, nN);
    gemm2_kernel<8, 128, 2, 16, 8, 1><<<(nN + 15) / 16, 256>>>(p_in8, ew1, eb1, p_t1, nN, 128, 0);
    gemm_mma_kernel<128, 128, 1><<<(nN + 127) / 128, 256, G128_SMEM>>>(p_t1, ew2, eb2, p_t2, nN);
    gemm_mma_kernel<128, 64, 1><<<(nN + 127) / 128, 256, G64_SMEM>>>(p_t2, ew3, eb3, p_h, nN);

    // ---- 3 CGConv layers ----
    for (int L = 0; L < 3; ++L) {
        const float* wf = (const float*)d_in[11 + 4 * L];
        const float* bf = (const float*)d_in[12 + 4 * L];
        const float* ws = (const float*)d_in[13 + 4 * L];
        const float* bs = (const float*)d_in[14 + 4 * L];
        convproj_mma_kernel<<<(nN + 63) / 64, 256, CP_DYN_TOTAL>>>(p_h, wf, bf, bs, ws,
                                                                   p_D, p_Sh, nN);
        if (L == 0) cudaStreamWaitEvent(0, evJoin, 0);   // join: edge2 needs CSR
        edge2_kernel<<<(nN + 7) / 8, 256>>>((const float4*)p_D, (const uint2*)p_Sh, p_h,
                                            p_rowstart, p_E,
                                            wf + 128 * 64, ws + 128 * 64,
                                            nN, L < 2 ? 1 : 0);
    }

    // ---- readout ----
    gemm_mma_kernel<64, 64, 2><<<(nN + 127) / 128, 256, G64_SMEM>>>(p_h, dw1, db1, p_t3, nN);
    desc2_kernel<<<1024, 256>>>(p_t3, dw2, db2, (float*)d_out, nN);
}

// round 16
// speedup vs baseline: 1.1245x; 1.1245x over previous
#include <cuda_runtime.h>
#include <cuda_fp16.h>
#include <math.h>

#define NNODES 50000
#define NEDGES 1200000
#define SCAN_TILE 1024
#define SCAN_BLOCKS ((NNODES + SCAN_TILE - 1) / SCAN_TILE)

// ---------------- scratch (device globals: no allocation allowed) ----------------
__device__ float g_in8[NNODES * 8];
__device__ float g_t1[NNODES * 128];
__device__ float g_t2[NNODES * 128];
__device__ float g_h[NNODES * 64];      // current node features
__device__ float g_D[NNODES * 128];     // packed dst proj fp32; f-halves pre-scaled by 0.5
__device__ unsigned g_Sh[NNODES * 64];  // packed src proj fp16: [2l]=h2(f)*0.5, [2l+1]=h2(s)
__device__ float g_t3[NNODES * 64];     // readout hidden
__device__ int   g_cnt[NNODES * 2];     // [deg | cursor]
__device__ int   g_rowstart[NNODES + 1];
__device__ int   g_blocksum[SCAN_BLOCKS + 1];
__device__ uint4 g_E[NEDGES];           // {src | klo<<20, h2(g0,g1), h2(g2,g3), h2(g4,0)}

__device__ __forceinline__ unsigned h2_bits(__half2 h) { return *reinterpret_cast<unsigned*>(&h); }
__device__ __forceinline__ __half2 bits_h2(unsigned u) { return *reinterpret_cast<__half2*>(&u); }

__device__ __forceinline__ void ldsm4(unsigned& r0, unsigned& r1, unsigned& r2, unsigned& r3, unsigned addr) {
    asm volatile("ldmatrix.sync.aligned.m8n8.x4.shared.b16 {%0,%1,%2,%3}, [%4];"
                 : "=r"(r0), "=r"(r1), "=r"(r2), "=r"(r3) : "r"(addr));
}
__device__ __forceinline__ void ldsm4t(unsigned& r0, unsigned& r1, unsigned& r2, unsigned& r3, unsigned addr) {
    asm volatile("ldmatrix.sync.aligned.m8n8.x4.trans.shared.b16 {%0,%1,%2,%3}, [%4];"
                 : "=r"(r0), "=r"(r1), "=r"(r2), "=r"(r3) : "r"(addr));
}
__device__ __forceinline__ void mma16816(float* c, unsigned a0, unsigned a1, unsigned a2, unsigned a3,
                                         unsigned b0, unsigned b1) {
    asm volatile("mma.sync.aligned.m16n8k16.row.col.f32.f16.f16.f32 "
                 "{%0,%1,%2,%3}, {%4,%5,%6,%7}, {%8,%9}, {%0,%1,%2,%3};"
                 : "+f"(c[0]), "+f"(c[1]), "+f"(c[2]), "+f"(c[3])
                 : "r"(a0), "r"(a1), "r"(a2), "r"(a3), "r"(b0), "r"(b1));
}

// pack fp32 pair -> hi/lo fp16 half2 words
__device__ __forceinline__ void pack_hilo(float a, float b, unsigned& hi, unsigned& lo) {
    __half h0 = __float2half_rn(a), h1 = __float2half_rn(b);
    hi = h2_bits(__halves2half2(h0, h1));
    lo = h2_bits(__halves2half2(__float2half_rn(a - __half2float(h0)),
                                __float2half_rn(b - __half2float(h1))));
}

// dynamic smem layout for convproj (hi/lo split tiles)
#define CP_A_BYTES (64 * 72 * 2)      // 9216
#define CP_B_BYTES (64 * 264 * 2)     // 33792
#define CP_DYN_TOTAL (2 * (CP_A_BYTES + CP_B_BYTES))  // 86016

// ---------------- concat [x|forces_stack|forces_norm] -> [N,8] ----------------
__global__ void concat_kernel(const float* __restrict__ x, const float* __restrict__ fs,
                              const float* __restrict__ fn, float* __restrict__ out, int n) {
    int i = blockIdx.x * blockDim.x + threadIdx.x;
    if (i >= n) return;
    float4 xv = *reinterpret_cast<const float4*>(&x[i * 4]);
    out[i * 8 + 0] = xv.x;
    out[i * 8 + 1] = xv.y;
    out[i * 8 + 2] = xv.z;
    out[i * 8 + 3] = xv.w;
    out[i * 8 + 4] = fs[i * 3 + 0];
    out[i * 8 + 5] = fs[i * 3 + 1];
    out[i * 8 + 6] = fs[i * 3 + 2];
    out[i * 8 + 7] = fn[i];
}

// ---------------- CSR build ----------------
__global__ void zero_int_kernel(int* __restrict__ p, int n) {
    int i = blockIdx.x * blockDim.x + threadIdx.x;
    if (i < n) p[i] = 0;
}

__global__ void hist_kernel(const int* __restrict__ dst, int* __restrict__ deg, int ne) {
    int e = blockIdx.x * blockDim.x + threadIdx.x;
    if (e < ne) atomicAdd(&deg[dst[e]], 1);
}

__global__ void scanA_kernel(const int* __restrict__ deg, int* __restrict__ rowstart,
                             int* __restrict__ blocksum, int nN) {
    __shared__ int warpsums[32];
    int tid = threadIdx.x;
    int lane = tid & 31, wid = tid >> 5;
    int i = blockIdx.x * SCAN_TILE + tid;
    int v = (i < nN) ? deg[i] : 0;
    int x = v;
#pragma unroll
    for (int o = 1; o < 32; o <<= 1) {
        int t = __shfl_up_sync(0xffffffffu, x, o);
        if (lane >= o) x += t;
    }
    if (lane == 31) warpsums[wid] = x;
    __syncthreads();
    if (wid == 0) {
        int y = warpsums[lane];
#pragma unroll
        for (int o = 1; o < 32; o <<= 1) {
            int t = __shfl_up_sync(0xffffffffu, y, o);
            if (lane >= o) y += t;
        }
        warpsums[lane] = y;
    }
    __syncthreads();
    int incl = x + (wid ? warpsums[wid - 1] : 0);
    if (i < nN) rowstart[i] = incl;
    if (tid == SCAN_TILE - 1) blocksum[blockIdx.x] = incl;
}

// phase B: parallel exclusive scan of tile sums (nblocks <= 64)
__global__ void scanB_kernel(int* __restrict__ blocksum, int* __restrict__ rowstart,
                             int nblocks, int nN) {
    __shared__ int w0sum;
    int tid = threadIdx.x;      // 64 threads
    int lane = tid & 31;
    int v = (tid < nblocks) ? blocksum[tid] : 0;
    int x = v;
#pragma unroll
    for (int o = 1; o < 32; o <<= 1) {
        int t = __shfl_up_sync(0xffffffffu, x, o);
        if (lane >= o) x += t;
    }
    if (tid == 31) w0sum = x;
    __syncthreads();
    if (tid >= 32) x += w0sum;
    if (tid < nblocks) blocksum[tid] = x - v;   // exclusive
    if (tid == nblocks - 1) rowstart[nN] = x;   // total
}

__global__ void scanC_kernel(const int* __restrict__ deg, int* __restrict__ rowstart,
                             const int* __restrict__ blocksum, int nN) {
    int i = blockIdx.x * SCAN_TILE + threadIdx.x;
    if (i < nN) rowstart[i] = rowstart[i] - deg[i] + blocksum[blockIdx.x];
}

// scatter edges into CSR order (by dst) + precompute 5-term gaussian window (fp16 packed)
__global__ void scatter_kernel(const int* __restrict__ src, const int* __restrict__ dst,
                               const float* __restrict__ elen,
                               const int* __restrict__ rowstart, int* __restrict__ cursor,
                               uint4* __restrict__ E, int ne) {
    int e = blockIdx.x * blockDim.x + threadIdx.x;
    if (e >= ne) return;
    int dv = dst[e];
    int slot = rowstart[dv] + atomicAdd(&cursor[dv], 1);
    float d = elen[e];
    int k0 = (int)rintf(d * 5.0f);
    int klo = min(max(k0 - 2, 0), 21);
    float g[5];
#pragma unroll
    for (int j = 0; j < 5; ++j) {
        float dm = d - (float)(klo + j) * 0.2f;
        g[j] = __expf(-25.0f * dm * dm);
    }
    uint4 rec;
    rec.x = (unsigned)src[e] | ((unsigned)klo << 20);
    rec.y = h2_bits(__floats2half2_rn(g[0], g[1]));
    rec.z = h2_bits(__floats2half2_rn(g[2], g[3]));
    rec.w = h2_bits(__floats2half2_rn(g[4], 0.0f));
    E[slot] = rec;
}

// ---------------- node GEMM v2 (scalar, kept for embed layer1 only) ----------------
template <int K, int J, int YB, int NB, int KT, int ACT>
__global__ void __launch_bounds__(J * YB) gemm2_kernel(const float* __restrict__ in,
                                                       const float* __restrict__ W,
                                                       const float* __restrict__ bias,
                                                       float* __restrict__ out, int nN,
                                                       int ostride, int ocol) {
    constexpr int NBY = NB / YB;
    __shared__ float sIn[NB][K];
    __shared__ float sW[KT][J];
    int tid = threadIdx.x;
    int col = tid % J;
    int ys = tid / J;
    int nb = blockIdx.x * NB;

    for (int idx = tid * 4; idx < NB * K; idx += J * YB * 4) {
        int n = idx / K, k = idx % K;
        int gn = nb + n;
        float4 v = (gn < nN) ? *reinterpret_cast<const float4*>(&in[gn * K + k])
                             : make_float4(0.f, 0.f, 0.f, 0.f);
        *reinterpret_cast<float4*>(&sIn[n][k]) = v;
    }
    float bv = bias ? __ldg(&bias[col]) : 0.0f;
    float acc[NBY];
#pragma unroll
    for (int n = 0; n < NBY; n++) acc[n] = bv;

    for (int k0 = 0; k0 < K; k0 += KT) {
        __syncthreads();
        for (int r = ys; r < KT; r += YB) sW[r][col] = W[(k0 + r) * J + col];
        __syncthreads();
#pragma unroll
        for (int k = 0; k < KT; k += 4) {
            float w0 = sW[k][col], w1 = sW[k + 1][col], w2 = sW[k + 2][col], w3 = sW[k + 3][col];
#pragma unroll
            for (int n = 0; n < NBY; ++n) {
                float4 v = *reinterpret_cast<const float4*>(&sIn[ys * NBY + n][k0 + k]);
                float a = acc[n];
                a = fmaf(v.x, w0, a);
                a = fmaf(v.y, w1, a);
                a = fmaf(v.z, w2, a);
                a = fmaf(v.w, w3, a);
                acc[n] = a;
            }
        }
    }
#pragma unroll
    for (int n = 0; n < NBY; n++) {
        int gn = nb + ys * NBY + n;
        if (gn < nN) {
            float v = acc[n];
            if (ACT == 1) v = v > 0.0f ? v : 0.01f * v;   // leaky
            else if (ACT == 2) v = fmaxf(v, 0.0f);        // relu
            out[gn * ostride + ocol + col] = v;
        }
    }
}

// ---------------- generic split-precision MMA node GEMM ----------------
template <int K, int J, int ACT>
__global__ void __launch_bounds__(256) gemm_mma_kernel(const float* __restrict__ in,
                                                       const float* __restrict__ W,
                                                       const float* __restrict__ bias,
                                                       float* __restrict__ out, int nN) {
    constexpr int AB = 128 * 72 * 2;
    constexpr int BB = 64 * (J + 8) * 2;
    constexpr int NT8 = J / 8;
    extern __shared__ __align__(16) char dynsmem[];
    __half (*sAh)[72] = reinterpret_cast<__half(*)[72]>(dynsmem);
    __half (*sAl)[72] = reinterpret_cast<__half(*)[72]>(dynsmem + AB);
    __half (*sBh)[J + 8] = reinterpret_cast<__half(*)[J + 8]>(dynsmem + 2 * AB);
    __half (*sBl)[J + 8] = reinterpret_cast<__half(*)[J + 8]>(dynsmem + 2 * AB + BB);

    int tid = threadIdx.x;
    int nb = blockIdx.x * 128;
    int w = tid >> 5, lane = tid & 31;
    int mrow = w << 4;
    int q = lane >> 3, rr = lane & 7;

    float acc[NT8][4];
#pragma unroll
    for (int i = 0; i < NT8; ++i)
#pragma unroll
        for (int j = 0; j < 4; ++j) acc[i][j] = 0.0f;

    for (int kc = 0; kc < K; kc += 64) {
        __syncthreads();
        for (int idx = tid * 4; idx < 128 * 64; idx += 1024) {
            int n = idx >> 6, k = idx & 63;
            int gn = nb + n;
            float4 v = (gn < nN) ? *reinterpret_cast<const float4*>(&in[gn * K + kc + k])
                                 : make_float4(0.f, 0.f, 0.f, 0.f);
            unsigned hx, lx, hy, ly;
            pack_hilo(v.x, v.y, hx, lx);
            pack_hilo(v.z, v.w, hy, ly);
            *reinterpret_cast<uint2*>(&sAh[n][k]) = make_uint2(hx, hy);
            *reinterpret_cast<uint2*>(&sAl[n][k]) = make_uint2(lx, ly);
        }
        for (int idx = tid * 4; idx < 64 * J; idx += 1024) {
            int r = idx / J, j = idx % J;
            float4 v = *reinterpret_cast<const float4*>(&W[(kc + r) * J + j]);
            unsigned hx, lx, hy, ly;
            pack_hilo(v.x, v.y, hx, lx);
            pack_hilo(v.z, v.w, hy, ly);
            *reinterpret_cast<uint2*>(&sBh[r][j]) = make_uint2(hx, hy);
            *reinterpret_cast<uint2*>(&sBl[r][j]) = make_uint2(lx, ly);
        }
        __syncthreads();

#pragma unroll
        for (int ks = 0; ks < 4; ++ks) {
            int kk = ks << 4;
            unsigned a0, a1, a2, a3, c0, c1, c2, c3;
            int ar = mrow + (lane & 15), ac = kk + ((lane >> 4) << 3);
            ldsm4(a0, a1, a2, a3, (unsigned)__cvta_generic_to_shared(&sAh[ar][ac]));
            ldsm4(c0, c1, c2, c3, (unsigned)__cvta_generic_to_shared(&sAl[ar][ac]));
#pragma unroll
            for (int nt2 = 0; nt2 < J / 16; ++nt2) {
                int n0 = nt2 << 4;
                int br = kk + rr + ((q & 1) << 3), bc = n0 + ((q >> 1) << 3);
                unsigned b0, b1, b2, b3, d0, d1, d2, d3;
                ldsm4t(b0, b1, b2, b3, (unsigned)__cvta_generic_to_shared(&sBh[br][bc]));
                ldsm4t(d0, d1, d2, d3, (unsigned)__cvta_generic_to_shared(&sBl[br][bc]));
                mma16816(acc[nt2 * 2], a0, a1, a2, a3, b0, b1);
                mma16816(acc[nt2 * 2], a0, a1, a2, a3, d0, d1);
                mma16816(acc[nt2 * 2], c0, c1, c2, c3, b0, b1);
                mma16816(acc[nt2 * 2 + 1], a0, a1, a2, a3, b2, b3);
                mma16816(acc[nt2 * 2 + 1], a0, a1, a2, a3, d2, d3);
                mma16816(acc[nt2 * 2 + 1], c0, c1, c2, c3, b2, b3);
            }
        }
    }

    int r0 = lane >> 2;
    int cpair = (lane & 3) << 1;
    int gr0 = nb + mrow + r0;
    int gr1 = gr0 + 8;
#pragma unroll
    for (int nt = 0; nt < NT8; ++nt) {
        int col = (nt << 3) + cpair;
        float b0v = __ldg(&bias[col]), b1v = __ldg(&bias[col + 1]);
        float v00 = acc[nt][0] + b0v, v01 = acc[nt][1] + b1v;
        float v10 = acc[nt][2] + b0v, v11 = acc[nt][3] + b1v;
        if (ACT == 1) {
            v00 = v00 > 0.f ? v00 : 0.01f * v00;
            v01 = v01 > 0.f ? v01 : 0.01f * v01;
            v10 = v10 > 0.f ? v10 : 0.01f * v10;
            v11 = v11 > 0.f ? v11 : 0.01f * v11;
        } else if (ACT == 2) {
            v00 = fmaxf(v00, 0.f); v01 = fmaxf(v01, 0.f);
            v10 = fmaxf(v10, 0.f); v11 = fmaxf(v11, 0.f);
        }
        if (gr0 < nN) *reinterpret_cast<float2*>(&out[gr0 * J + col]) = make_float2(v00, v01);
        if (gr1 < nN) *reinterpret_cast<float2*>(&out[gr1 * J + col]) = make_float2(v10, v11);
    }
}

// ---------------- conv projections via split-precision tensor-core MMA ----------------
__global__ void __launch_bounds__(256) convproj_mma_kernel(const float* __restrict__ h,
                                                           const float* __restrict__ wf,
                                                           const float* __restrict__ bf,
                                                           const float* __restrict__ bs,
                                                           const float* __restrict__ ws,
                                                           float* __restrict__ D,
                                                           unsigned* __restrict__ Sh, int nN) {
    extern __shared__ __align__(16) char dynsmem[];
    __half (*sA)[72]  = reinterpret_cast<__half(*)[72]>(dynsmem);
    __half (*sAl)[72] = reinterpret_cast<__half(*)[72]>(dynsmem + CP_A_BYTES);
    __half (*sB)[264]  = reinterpret_cast<__half(*)[264]>(dynsmem + 2 * CP_A_BYTES);
    __half (*sBl)[264] = reinterpret_cast<__half(*)[264]>(dynsmem + 2 * CP_A_BYTES + CP_B_BYTES);
    int tid = threadIdx.x;
    int nb = blockIdx.x * 64;

    for (int idx = tid * 4; idx < 64 * 64; idx += 1024) {
        int n = idx >> 6, k = idx & 63;
        int gn = nb + n;
        float4 v = (gn < nN) ? *reinterpret_cast<const float4*>(&h[gn * 64 + k])
                             : make_float4(0.f, 0.f, 0.f, 0.f);
        unsigned hx, lx, hy, ly;
        pack_hilo(v.x, v.y, hx, lx);
        pack_hilo(v.z, v.w, hy, ly);
        *reinterpret_cast<uint2*>(&sA[n][k]) = make_uint2(hx, hy);
        *reinterpret_cast<uint2*>(&sAl[n][k]) = make_uint2(lx, ly);
    }
    // B tile: vectorized float4 loads, uint2 stores (j stride 4)
    for (int i = tid * 4; i < 128 * 64; i += 1024) {
        int r = i >> 6, j = i & 63;
        int k = r & 63;
        int half128 = (r >> 6) << 7;   // 0 for dst, 128 for src
        float4 vf = *reinterpret_cast<const float4*>(&wf[i]);
        float4 vs = *reinterpret_cast<const float4*>(&ws[i]);
        unsigned hx, lx, hy, ly;
        pack_hilo(0.5f * vf.x, 0.5f * vf.y, hx, lx);
        pack_hilo(0.5f * vf.z, 0.5f * vf.w, hy, ly);
        *reinterpret_cast<uint2*>(&sB[k][half128 + j]) = make_uint2(hx, hy);
        *reinterpret_cast<uint2*>(&sBl[k][half128 + j]) = make_uint2(lx, ly);
        pack_hilo(vs.x, vs.y, hx, lx);
        pack_hilo(vs.z, vs.w, hy, ly);
        *reinterpret_cast<uint2*>(&sB[k][half128 + 64 + j]) = make_uint2(hx, hy);
        *reinterpret_cast<uint2*>(&sBl[k][half128 + 64 + j]) = make_uint2(lx, ly);
    }
    __syncthreads();

    int w = tid >> 5, lane = tid & 31;
    int mrow = (w & 3) << 4;
    int nbase = (w >> 2) << 7;

    float acc[16][4];
#pragma unroll
    for (int i = 0; i < 16; ++i)
#pragma unroll
        for (int j = 0; j < 4; ++j) acc[i][j] = 0.0f;

    int q = lane >> 3, rr = lane & 7;
#pragma unroll
    for (int ks = 0; ks < 4; ++ks) {
        int kk = ks << 4;
        unsigned a0, a1, a2, a3, c0, c1, c2, c3;
        int ar = mrow + (lane & 15), ac = kk + ((lane >> 4) << 3);
        ldsm4(a0, a1, a2, a3, (unsigned)__cvta_generic_to_shared(&sA[ar][ac]));
        ldsm4(c0, c1, c2, c3, (unsigned)__cvta_generic_to_shared(&sAl[ar][ac]));
#pragma unroll
        for (int nt2 = 0; nt2 < 8; ++nt2) {
            int n0 = nbase + (nt2 << 4);
            int br = kk + rr + ((q & 1) << 3), bc = n0 + ((q >> 1) << 3);
            unsigned b0, b1, b2, b3, d0, d1, d2, d3;
            ldsm4t(b0, b1, b2, b3, (unsigned)__cvta_generic_to_shared(&sB[br][bc]));
            ldsm4t(d0, d1, d2, d3, (unsigned)__cvta_generic_to_shared(&sBl[br][bc]));
            mma16816(acc[nt2 * 2], a0, a1, a2, a3, b0, b1);
            mma16816(acc[nt2 * 2], a0, a1, a2, a3, d0, d1);
            mma16816(acc[nt2 * 2], c0, c1, c2, c3, b0, b1);
            mma16816(acc[nt2 * 2 + 1], a0, a1, a2, a3, b2, b3);
            mma16816(acc[nt2 * 2 + 1], a0, a1, a2, a3, d2, d3);
            mma16816(acc[nt2 * 2 + 1], c0, c1, c2, c3, b2, b3);
        }
    }

    int r0 = lane >> 2;
    int cpair = (lane & 3) << 1;
    int gr0 = nb + mrow + r0;
    int gr1 = gr0 + 8;
#pragma unroll
    for (int nt = 0; nt < 16; ++nt) {
        int nl = (nt << 3) + cpair;
        if (nbase == 0) {
            float b0v, b1v;
            int po;
            if (nl < 64) { b0v = 0.5f * __ldg(&bf[nl]); b1v = 0.5f * __ldg(&bf[nl + 1]); po = 2 * nl; }
            else         { b0v = __ldg(&bs[nl - 64]);   b1v = __ldg(&bs[nl - 63]);       po = 2 * nl - 126; }
            if (gr0 < nN)
                *reinterpret_cast<float2*>(&D[gr0 * 128 + po]) = make_float2(acc[nt][0] + b0v, acc[nt][1] + b1v);
            if (gr1 < nN)
                *reinterpret_cast<float2*>(&D[gr1 * 128 + po]) = make_float2(acc[nt][2] + b0v, acc[nt][3] + b1v);
        } else {
            int word = (nl < 64) ? nl : (nl - 63);
            if (gr0 < nN) Sh[gr0 * 64 + word] = h2_bits(__floats2half2_rn(acc[nt][0], acc[nt][1]));
            if (gr1 < nN) Sh[gr1 * 64 + word] = h2_bits(__floats2half2_rn(acc[nt][2], acc[nt][3]));
        }
    }
}

// ---------------- edge kernel: warp per dst node, half2 HFMA2 pipeline (R12 body) ----------------
__global__ void __launch_bounds__(256) edge2_kernel(const float4* __restrict__ D4,
                                                    const uint2* __restrict__ S2,
                                                    float* __restrict__ h,
                                                    const int* __restrict__ rowstart,
                                                    const uint4* __restrict__ E,
                                                    const float* __restrict__ wfe,
                                                    const float* __restrict__ wse,
                                                    int nN, int act) {
    __shared__ uint2 sW2[26][32];
    int tid = threadIdx.x;
    for (int idx = tid; idx < 26 * 32; idx += 256) {
        int k = idx >> 5, l = idx & 31;
        uint2 p;
        p.x = h2_bits(__floats2half2_rn(0.5f * wfe[k * 64 + 2 * l], 0.5f * wfe[k * 64 + 2 * l + 1]));
        p.y = h2_bits(__floats2half2_rn(wse[k * 64 + 2 * l], wse[k * 64 + 2 * l + 1]));
        sW2[k][l] = p;
    }
    __syncthreads();

    int lane = tid & 31;
    int node = blockIdx.x * 8 + (tid >> 5);
    if (node >= nN) return;
    int c2 = lane << 1;

    const float4 a4 = __ldg(&D4[node * 32 + lane]);  // (0.5*af.x, 0.5*af.y, as.x, as.y)
    const float2 hm = *reinterpret_cast<const float2*>(&h[node * 64 + c2]);
    float mx = 0.0f, my = 0.0f;

    int rs = __ldg(&rowstart[node]);
    int re = __ldg(&rowstart[node + 1]);
#pragma unroll 2
    for (int s = rs; s < re; ++s) {
        uint4 rec = __ldg(&E[s]);
        int sv = (int)(rec.x & 0xFFFFFu);
        int klo = (int)(rec.x >> 20);
        uint2 sb = __ldg(&S2[sv * 32 + lane]);
        __half2 g01 = bits_h2(rec.y);
        __half2 g23 = bits_h2(rec.z);
        __half2 g4h = bits_h2(rec.w);

        __half2 ef = bits_h2(sb.x);
        __half2 es = bits_h2(sb.y);
        const uint2* wp = &sW2[klo][lane];
        uint2 wv;
        __half2 gb;
        wv = wp[0];   gb = __low2half2(g01);  ef = __hfma2(gb, bits_h2(wv.x), ef); es = __hfma2(gb, bits_h2(wv.y), es);
        wv = wp[32];  gb = __high2half2(g01); ef = __hfma2(gb, bits_h2(wv.x), ef); es = __hfma2(gb, bits_h2(wv.y), es);
        wv = wp[64];  gb = __low2half2(g23);  ef = __hfma2(gb, bits_h2(wv.x), ef); es = __hfma2(gb, bits_h2(wv.y), es);
        wv = wp[96];  gb = __high2half2(g23); ef = __hfma2(gb, bits_h2(wv.x), ef); es = __hfma2(gb, bits_h2(wv.y), es);
        wv = wp[128]; gb = __low2half2(g4h);  ef = __hfma2(gb, bits_h2(wv.x), ef); es = __hfma2(gb, bits_h2(wv.y), es);

        float2 ef2 = __half22float2(ef);
        float2 es2 = __half22float2(es);
        float zfx = a4.x + ef2.x;   // already z/2 for the sigmoid channel
        float zfy = a4.y + ef2.y;
        float zsx = a4.z + es2.x;
        float zsy = a4.w + es2.y;

        float tx, ty;
        asm("tanh.approx.f32 %0, %1;" : "=f"(tx) : "f"(zfx));
        asm("tanh.approx.f32 %0, %1;" : "=f"(ty) : "f"(zfy));
        float sgx = fmaf(tx, 0.5f, 0.5f);
        float sgy = fmaf(ty, 0.5f, 0.5f);
        // guarded softplus: linear branch doubles as overflow clamp (z>15: err < 3e-7)
        float spx = (zsx > 15.0f) ? zsx : __logf(1.0f + __expf(zsx));
        float spy = (zsy > 15.0f) ? zsy : __logf(1.0f + __expf(zsy));

        mx = fmaf(sgx, spx, mx);
        my = fmaf(sgy, spy, my);
    }
    float ox = hm.x + mx, oy = hm.y + my;
    if (act) {
        ox = ox > 0.0f ? ox : 0.01f * ox;
        oy = oy > 0.0f ? oy : 0.01f * oy;
    }
    *reinterpret_cast<float2*>(&h[node * 64 + c2]) = make_float2(ox, oy);
}

// ---------------- readout layer 2: [N,64] @ [64,3] + b, warp per node ----------------
__global__ void desc2_kernel(const float* __restrict__ t3, const float* __restrict__ w2,
                             const float* __restrict__ b2, float* __restrict__ out, int n) {
    __shared__ float sw[192];
    __shared__ float sb[3];
    if (threadIdx.x < 192) sw[threadIdx.x] = w2[threadIdx.x];
    if (threadIdx.x < 3) sb[threadIdx.x] = b2[threadIdx.x];
    __syncthreads();
    int lane = threadIdx.x & 31;
    int gw = blockIdx.x * (blockDim.x >> 5) + (threadIdx.x >> 5);
    int nw = gridDim.x * (blockDim.x >> 5);
    for (int node = gw; node < n; node += nw) {
        float p0 = 0.f, p1 = 0.f, p2 = 0.f;
        for (int k = lane; k < 64; k += 32) {
            float v = t3[node * 64 + k];
            p0 = fmaf(v, sw[k * 3 + 0], p0);
            p1 = fmaf(v, sw[k * 3 + 1], p1);
            p2 = fmaf(v, sw[k * 3 + 2], p2);
        }
        for (int off = 16; off; off >>= 1) {
            p0 += __shfl_down_sync(0xffffffffu, p0, off);
            p1 += __shfl_down_sync(0xffffffffu, p1, off);
            p2 += __shfl_down_sync(0xffffffffu, p2, off);
        }
        if (lane == 0) {
            out[node * 3 + 0] = p0 + sb[0];
            out[node * 3 + 1] = p1 + sb[1];
            out[node * 3 + 2] = p2 + sb[2];
        }
    }
}

extern "C" void kernel_launch(void* const* d_in, const int* in_sizes, int n_in,
                              void* d_out, int out_size) {
    const float* x    = (const float*)d_in[0];
    const float* fs   = (const float*)d_in[1];
    const float* fn   = (const float*)d_in[2];
    const int*   eidx = (const int*)d_in[3];
    const float* elen = (const float*)d_in[4];
    const float* ew1 = (const float*)d_in[5];  const float* eb1 = (const float*)d_in[6];
    const float* ew2 = (const float*)d_in[7];  const float* eb2 = (const float*)d_in[8];
    const float* ew3 = (const float*)d_in[9];  const float* eb3 = (const float*)d_in[10];
    const float* dw1 = (const float*)d_in[23]; const float* db1 = (const float*)d_in[24];
    const float* dw2 = (const float*)d_in[25]; const float* db2 = (const float*)d_in[26];

    int nN = in_sizes[0] / 4;
    int nE = in_sizes[4];
    const int* src = eidx;
    const int* dst = eidx + nE;

    float *p_in8, *p_t1, *p_t2, *p_h, *p_D, *p_t3;
    unsigned* p_Sh;
    int *p_cnt, *p_rowstart, *p_blocksum;
    uint4* p_E;
    cudaGetSymbolAddress((void**)&p_in8, g_in8);
    cudaGetSymbolAddress((void**)&p_t1, g_t1);
    cudaGetSymbolAddress((void**)&p_t2, g_t2);
    cudaGetSymbolAddress((void**)&p_h, g_h);
    cudaGetSymbolAddress((void**)&p_D, g_D);
    cudaGetSymbolAddress((void**)&p_Sh, g_Sh);
    cudaGetSymbolAddress((void**)&p_t3, g_t3);
    cudaGetSymbolAddress((void**)&p_cnt, g_cnt);
    cudaGetSymbolAddress((void**)&p_rowstart, g_rowstart);
    cudaGetSymbolAddress((void**)&p_blocksum, g_blocksum);
    cudaGetSymbolAddress((void**)&p_E, g_E);

    // dynamic smem opt-ins (host-side, capture-safe)
    cudaFuncSetAttribute(convproj_mma_kernel, cudaFuncAttributeMaxDynamicSharedMemorySize,
                         CP_DYN_TOTAL);
    constexpr int G128_SMEM = 2 * (128 * 72 * 2) + 2 * (64 * 136 * 2);  // 71680
    constexpr int G64_SMEM  = 2 * (128 * 72 * 2) + 2 * (64 * 72 * 2);   // 55296
    cudaFuncSetAttribute((const void*)gemm_mma_kernel<128, 128, 1>,
                         cudaFuncAttributeMaxDynamicSharedMemorySize, G128_SMEM);
    cudaFuncSetAttribute((const void*)gemm_mma_kernel<128, 64, 1>,
                         cudaFuncAttributeMaxDynamicSharedMemorySize, G64_SMEM);
    cudaFuncSetAttribute((const void*)gemm_mma_kernel<64, 64, 2>,
                         cudaFuncAttributeMaxDynamicSharedMemorySize, G64_SMEM);

    int* p_deg = p_cnt;
    int* p_cur = p_cnt + NNODES;
    int nsb = (nN + SCAN_TILE - 1) / SCAN_TILE;

    // ---- fork: CSR chain on side stream, embed chain on main stream ----
    cudaStream_t sCsr;
    cudaEvent_t evFork, evJoin;
    cudaStreamCreateWithFlags(&sCsr, cudaStreamNonBlocking);
    cudaEventCreateWithFlags(&evFork, cudaEventDisableTiming);
    cudaEventCreateWithFlags(&evJoin, cudaEventDisableTiming);
    cudaEventRecord(evFork, 0);
    cudaStreamWaitEvent(sCsr, evFork, 0);

    // CSR chain (side stream)
    zero_int_kernel<<<(2 * nN + 255) / 256, 256, 0, sCsr>>>(p_cnt, 2 * nN);
    hist_kernel<<<(nE + 255) / 256, 256, 0, sCsr>>>(dst, p_deg, nE);
    scanA_kernel<<<nsb, SCAN_TILE, 0, sCsr>>>(p_deg, p_rowstart, p_blocksum, nN);
    scanB_kernel<<<1, 64, 0, sCsr>>>(p_blocksum, p_rowstart, nsb, nN);
    scanC_kernel<<<nsb, SCAN_TILE, 0, sCsr>>>(p_deg, p_rowstart, p_blocksum, nN);
    scatter_kernel<<<(nE + 255) / 256, 256, 0, sCsr>>>(src, dst, elen, p_rowstart, p_cur, p_E, nE);
    cudaEventRecord(evJoin, sCsr);

    // embed chain (main stream)
    concat_kernel<<<(nN + 255) / 256, 256>>>(x, fs, fn, p_in8, nN);
    gemm2_kernel<8, 128, 2, 16, 8, 1><<<(nN + 15) / 16, 256>>>(p_in8, ew1, eb1, p_t1, nN, 128, 0);
    gemm_mma_kernel<128, 128, 1><<<(nN + 127) / 128, 256, G128_SMEM>>>(p_t1, ew2, eb2, p_t2, nN);
    gemm_mma_kernel<128, 64, 1><<<(nN + 127) / 128, 256, G64_SMEM>>>(p_t2, ew3, eb3, p_h, nN);

    // ---- 3 CGConv layers ----
    for (int L = 0; L < 3; ++L) {
        const float* wf = (const float*)d_in[11 + 4 * L];
        const float* bf = (const float*)d_in[12 + 4 * L];
        const float* ws = (const float*)d_in[13 + 4 * L];
        const float* bs = (const float*)d_in[14 + 4 * L];
        convproj_mma_kernel<<<(nN + 63) / 64, 256, CP_DYN_TOTAL>>>(p_h, wf, bf, bs, ws,
                                                                   p_D, p_Sh, nN);
        if (L == 0) cudaStreamWaitEvent(0, evJoin, 0);   // join: edge2 needs CSR
        edge2_kernel<<<(nN + 7) / 8, 256>>>((const float4*)p_D, (const uint2*)p_Sh, p_h,
                                            p_rowstart, p_E,
                                            wf + 128 * 64, ws + 128 * 64,
                                            nN, L < 2 ? 1 : 0);
    }

    // ---- readout ----
    gemm_mma_kernel<64, 64, 2><<<(nN + 127) / 128, 256, G64_SMEM>>>(p_h, dw1, db1, p_t3, nN);
    desc2_kernel<<<1024, 256>>>(p_t3, dw2, db2, (float*)d_out, nN);
}